// round 14
// baseline (speedup 1.0000x reference)
#include <cuda_runtime.h>
#include <cuda_bf16.h>
#include <mma.h>
#include <math.h>

using namespace nvcuda;

#define D 512
#define C 64
#define S 16
#define NS 1024
#define Q 2048
#define REGP 0.1f
#define PADK 72    // bf16 smem row stride for 64-wide k-chunks (mult of 8)
#define YSTR 136   // fp32 Y smem row stride (MUST be mult of 4 for wmma store)

// ---------------- scratch (device globals: zero-initialized at load) --------
__device__ float g_L[D * D];
__device__ float g_base[D * D];
__device__ float g_mu[C * D];
__device__ float g_logdet[C];
__device__ int   g_idx[NS];
__device__ float g_sigma[(size_t)C * D * D];      // sigma -> cholesky L (lower)
__device__ float g_dinv[C * 16 * 32 * 32];        // inverses of 32x32 diag blocks
__device__ __nv_bfloat16 g_Th[(size_t)C * D * D]; // T = inv(L), bf16 hi (upper stays 0)
__device__ __nv_bfloat16 g_Tl[(size_t)C * D * D]; // T bf16 lo
__device__ __nv_bfloat16 g_Xh[(size_t)Q * D];     // Xq bf16 hi
__device__ __nv_bfloat16 g_Xl[(size_t)Q * D];     // Xq bf16 lo
__device__ float g_v[C * D];                      // v_c = T_c mu_c
__device__ float g_munorm[C];
__device__ float g_xnorm[Q];
__device__ float g_dot[(size_t)Q * C];            // Xq . mu_c
__device__ float g_dummy[(size_t)Q * C];          // probe output (never validated)

__device__ __forceinline__ float dev_kap(const float* kappa) {
    return fabsf(*kappa) + 1e-6f;
}
__device__ __forceinline__ float dev_nu(const float* nu) {
    float v = *nu;
    float lo = (float)(D - 1) + 1e-6f;
    return v < lo ? lo : v;
}

// ---------------- 1. deterministic stable bucketing ------------------------
__global__ void k_bucket(const int* __restrict__ labels) {
    int i = blockIdx.x * blockDim.x + threadIdx.x;
    if (i >= NS) return;
    int lab = labels[i];
    int pos = 0;
    for (int p = 0; p < i; p++) pos += (labels[p] == lab) ? 1 : 0;
    g_idx[lab * S + pos] = i;
}

// ---------------- 2. materialize L ------------------------------------------
__global__ void k_build_L(const float* __restrict__ tdiag, const float* __restrict__ tlow) {
    int i = blockIdx.x, j = threadIdx.x;
    float v;
    if (j == i)      v = fabsf(tdiag[i]);
    else if (j < i)  v = tlow[i * D + j];
    else             v = 0.f;
    g_L[i * D + j] = v;
}

// ---------------- 3. base = L L^T + kap m m^T (lower 64x64 tiles) -----------
__global__ void k_base(const float* __restrict__ m, const float* __restrict__ kappa) {
    int bi = blockIdx.x, bj = blockIdx.y;
    if (bi < bj) return;
    __shared__ float As[16][68], Bsm[16][68];
    int t = threadIdx.x;
    int tq = t % 16, ti = t / 16;
    int lrow = t / 4, jg = t % 4;
    float acc[4][4] = {};
    for (int k0 = 0; k0 < D; k0 += 16) {
        float4 a = *(const float4*)&g_L[(bi * 64 + lrow) * D + k0 + jg * 4];
        float4 b = *(const float4*)&g_L[(bj * 64 + lrow) * D + k0 + jg * 4];
        __syncthreads();
        As[jg * 4 + 0][lrow] = a.x; As[jg * 4 + 1][lrow] = a.y;
        As[jg * 4 + 2][lrow] = a.z; As[jg * 4 + 3][lrow] = a.w;
        Bsm[jg * 4 + 0][lrow] = b.x; Bsm[jg * 4 + 1][lrow] = b.y;
        Bsm[jg * 4 + 2][lrow] = b.z; Bsm[jg * 4 + 3][lrow] = b.w;
        __syncthreads();
#pragma unroll
        for (int k = 0; k < 16; k++) {
            float4 av = *(const float4*)&As[k][tq * 4];
            float4 bv = *(const float4*)&Bsm[k][ti * 4];
            float a4[4] = {av.x, av.y, av.z, av.w};
            float b4[4] = {bv.x, bv.y, bv.z, bv.w};
#pragma unroll
            for (int r = 0; r < 4; r++)
#pragma unroll
                for (int s2 = 0; s2 < 4; s2++) acc[r][s2] += a4[r] * b4[s2];
        }
    }
    float kap = dev_kap(kappa);
#pragma unroll
    for (int r = 0; r < 4; r++) {
        int di = bi * 64 + tq * 4 + r;
#pragma unroll
        for (int s2 = 0; s2 < 4; s2++) {
            int ej = bj * 64 + ti * 4 + s2;
            g_base[di * D + ej] = acc[r][s2] + kap * m[di] * m[ej];
        }
    }
}

// ---------------- 4. class means -> mu --------------------------------------
__global__ void k_mu(const float* __restrict__ Xs, const float* __restrict__ m,
                     const float* __restrict__ kappa) {
    int c = blockIdx.x, d = threadIdx.x;
    float s = 0.f;
#pragma unroll
    for (int ss = 0; ss < S; ss++) s += Xs[(size_t)g_idx[c * S + ss] * D + d];
    float mean = s / (float)S;
    float kap = dev_kap(kappa);
    g_mu[c * D + d] = (kap / (kap + (float)S)) * m[d] + ((float)S / (kap + (float)S)) * mean;
}

// ---------------- 5. sigma[c] (lower 64x64 tiles) ---------------------------
__global__ void k_sigma(const float* __restrict__ Xs, const float* __restrict__ kappa,
                        const float* __restrict__ nu) {
    int bi = blockIdx.x, bj = blockIdx.y, c = blockIdx.z;
    if (bi < bj) return;
    __shared__ float Xi[16][68], Xj[16][68];
    int t = threadIdx.x;
    int srow = t / 16, cg = t % 16;
    {
        int gi = g_idx[c * S + srow];
        float4 a = *(const float4*)&Xs[(size_t)gi * D + bi * 64 + cg * 4];
        float4 b = *(const float4*)&Xs[(size_t)gi * D + bj * 64 + cg * 4];
        Xi[srow][cg * 4 + 0] = a.x; Xi[srow][cg * 4 + 1] = a.y;
        Xi[srow][cg * 4 + 2] = a.z; Xi[srow][cg * 4 + 3] = a.w;
        Xj[srow][cg * 4 + 0] = b.x; Xj[srow][cg * 4 + 1] = b.y;
        Xj[srow][cg * 4 + 2] = b.z; Xj[srow][cg * 4 + 3] = b.w;
    }
    __syncthreads();
    int tq = t % 16, ti = t / 16;
    float acc[4][4] = {};
#pragma unroll
    for (int s = 0; s < 16; s++) {
        float4 av = *(const float4*)&Xi[s][tq * 4];
        float4 bv = *(const float4*)&Xj[s][ti * 4];
        float a4[4] = {av.x, av.y, av.z, av.w};
        float b4[4] = {bv.x, bv.y, bv.z, bv.w};
#pragma unroll
        for (int r = 0; r < 4; r++)
#pragma unroll
            for (int s2 = 0; s2 < 4; s2++) acc[r][s2] += a4[r] * b4[s2];
    }
    float kap = dev_kap(kappa);
    float nuv = dev_nu(nu);
    float kS = kap + (float)S;
    float scale = (kS + 1.f) / ((nuv + (float)S - (float)D + 1.f) * kS);
    float* sig = &g_sigma[(size_t)c * D * D];
#pragma unroll
    for (int r = 0; r < 4; r++) {
        int di = bi * 64 + tq * 4 + r;
        float mud = g_mu[c * D + di];
#pragma unroll
        for (int s2 = 0; s2 < 4; s2++) {
            int ej = bj * 64 + ti * 4 + s2;
            float v = g_base[di * D + ej] + acc[r][s2] - kS * mud * g_mu[c * D + ej];
            sig[(size_t)di * D + ej] = v * scale;
        }
    }
}

// ---------------- 6a. Cholesky panel step (diag factor + column solve) ------
__global__ void k_chol_panel(int kb) {
    int c = blockIdx.x;
    float* A = &g_sigma[(size_t)c * D * D];
    __shared__ float Ds[32][33];
    __shared__ float s_ld;
    int t = threadIdx.x;  // 256

    for (int e = t; e < 1024; e += 256) {
        int r = e / 32, cc = e % 32;
        Ds[r][cc] = A[(size_t)(kb * 32 + r) * D + kb * 32 + cc];
    }
    __syncthreads();
    if (t < 32) {
        int lane = t;
        for (int k = 0; k < 32; k++) {
            if (lane == k) Ds[k][k] = sqrtf(Ds[k][k]);
            __syncwarp();
            if (lane > k) Ds[lane][k] /= Ds[k][k];
            __syncwarp();
            for (int j = k + 1; j <= lane; j++)
                Ds[lane][j] -= Ds[lane][k] * Ds[j][k];
            __syncwarp();
        }
        float lv = logf(Ds[lane][lane]);
#pragma unroll
        for (int o = 16; o > 0; o >>= 1) lv += __shfl_down_sync(0xffffffffu, lv, o);
        if (lane == 0) s_ld = lv;
    }
    __syncthreads();
    for (int e = t; e < 1024; e += 256) {
        int r = e / 32, cc = e % 32;
        A[(size_t)(kb * 32 + r) * D + kb * 32 + cc] = (cc <= r) ? Ds[r][cc] : 0.f;
    }
    // panel rows below: solve x * Ds^T = a
    for (int r = (kb + 1) * 32 + t; r < D; r += 256) {
        float a[32];
#pragma unroll
        for (int j = 0; j < 32; j++) a[j] = A[(size_t)r * D + kb * 32 + j];
#pragma unroll
        for (int j = 0; j < 32; j++) {
            float sacc = a[j];
#pragma unroll
            for (int k2 = 0; k2 < 32; k2++)
                if (k2 < j) sacc -= a[k2] * Ds[j][k2];
            a[j] = sacc / Ds[j][j];
        }
#pragma unroll
        for (int j = 0; j < 32; j++) A[(size_t)r * D + kb * 32 + j] = a[j];
    }
    if (t == 0) {
        if (kb == 0) g_logdet[c] = 2.f * s_ld;
        else         g_logdet[c] += 2.f * s_ld;
    }
}

// ---------------- 6b. Cholesky trailing step: A[ib,jb] -= Pi Pj^T -----------
__global__ void __launch_bounds__(64) k_chol_trail(int kb) {
    int c = blockIdx.y;
    int p = blockIdx.x;
    int ib = kb + 1, rem = p;
    while (rem >= ib - kb) { rem -= (ib - kb); ib++; }
    int jb = kb + 1 + rem;

    float* A = &g_sigma[(size_t)c * D * D];
    __shared__ float Pi[32][33], Pj[32][33];
    int t = threadIdx.x;
    for (int e = t; e < 1024; e += 64) {
        int r = e / 32, cc = e % 32;
        Pi[r][cc] = A[(size_t)(ib * 32 + r) * D + kb * 32 + cc];
        Pj[r][cc] = A[(size_t)(jb * 32 + r) * D + kb * 32 + cc];
    }
    __syncthreads();
    int r0 = (t / 8) * 4, c0 = (t % 8) * 4;
    float acc[4][4] = {};
#pragma unroll
    for (int k2 = 0; k2 < 32; k2++) {
        float pi0 = Pi[r0 + 0][k2], pi1 = Pi[r0 + 1][k2];
        float pi2 = Pi[r0 + 2][k2], pi3 = Pi[r0 + 3][k2];
        float pj0 = Pj[c0 + 0][k2], pj1 = Pj[c0 + 1][k2];
        float pj2 = Pj[c0 + 2][k2], pj3 = Pj[c0 + 3][k2];
        acc[0][0] += pi0 * pj0; acc[0][1] += pi0 * pj1; acc[0][2] += pi0 * pj2; acc[0][3] += pi0 * pj3;
        acc[1][0] += pi1 * pj0; acc[1][1] += pi1 * pj1; acc[1][2] += pi1 * pj2; acc[1][3] += pi1 * pj3;
        acc[2][0] += pi2 * pj0; acc[2][1] += pi2 * pj1; acc[2][2] += pi2 * pj2; acc[2][3] += pi2 * pj3;
        acc[3][0] += pi3 * pj0; acc[3][1] += pi3 * pj1; acc[3][2] += pi3 * pj2; acc[3][3] += pi3 * pj3;
    }
#pragma unroll
    for (int r = 0; r < 4; r++)
#pragma unroll
        for (int s2 = 0; s2 < 4; s2++)
            A[(size_t)(ib * 32 + r0 + r) * D + jb * 32 + c0 + s2] -= acc[r][s2];
}

// ---------------- 7. invert 32x32 diagonal blocks of L ----------------------
__global__ void k_dinv() {
    int c = blockIdx.x;
    int blk = threadIdx.x / 32, lane = threadIdx.x % 32;
    const float* Lb = &g_sigma[(size_t)c * D * D + (size_t)(blk * 32) * D + blk * 32];
    float x[32];
#pragma unroll
    for (int i = 0; i < 32; i++) x[i] = 0.f;
#pragma unroll
    for (int i = 0; i < 32; i++) {
        float sacc = (i == lane) ? 1.f : 0.f;
#pragma unroll
        for (int k = 0; k < 32; k++)
            if (k < i) sacc -= Lb[(size_t)i * D + k] * x[k];
        x[i] = (i < lane) ? 0.f : sacc / Lb[(size_t)i * D + i];
    }
    float* out = &g_dinv[((size_t)c * 16 + blk) * 1024];
#pragma unroll
    for (int i = 0; i < 32; i++) out[i * 32 + lane] = x[i];
}

// ---------------- 8. T = inv(L) -> bf16 hi/lo split -------------------------
__global__ void k_tinv() {
    int jb = blockIdx.x, c = blockIdx.y;
    extern __shared__ float sm[];
    float* Xp = sm;                 // [16][32][33]
    float* Ls = sm + 16 * 1056;     // [32][33]
    float* Msh = Ls + 1056;         // [32][33]
    int t = threadIdx.x;
    int lane = t % 32, ig = t / 32;
    const float* A = &g_sigma[(size_t)c * D * D];
    const float* Dv = &g_dinv[(size_t)c * 16 * 1024];

    for (int e = t; e < 1024; e += 256) {
        int r = e / 32, cc = e % 32;
        Xp[jb * 1056 + r * 33 + cc] = Dv[jb * 1024 + r * 32 + cc];
    }
    __syncthreads();

    for (int ib = jb + 1; ib < 16; ib++) {
        float acc[4] = {0.f, 0.f, 0.f, 0.f};
        for (int kb = jb; kb < ib; kb++) {
            __syncthreads();
            for (int e = t; e < 1024; e += 256) {
                int r = e / 32, cc = e % 32;
                Ls[r * 33 + cc] = A[(size_t)(ib * 32 + r) * D + kb * 32 + cc];
            }
            __syncthreads();
#pragma unroll
            for (int k = 0; k < 32; k++) {
                float xv = Xp[kb * 1056 + k * 33 + lane];
#pragma unroll
                for (int r = 0; r < 4; r++) acc[r] += Ls[(ig * 4 + r) * 33 + k] * xv;
            }
        }
        __syncthreads();
#pragma unroll
        for (int r = 0; r < 4; r++) Msh[(ig * 4 + r) * 33 + lane] = acc[r];
        for (int e = t; e < 1024; e += 256) {
            int r = e / 32, cc = e % 32;
            Ls[r * 33 + cc] = Dv[ib * 1024 + r * 32 + cc];
        }
        __syncthreads();
        float acc2[4] = {0.f, 0.f, 0.f, 0.f};
#pragma unroll
        for (int k = 0; k < 32; k++) {
            float mv = Msh[k * 33 + lane];
#pragma unroll
            for (int r = 0; r < 4; r++) acc2[r] += Ls[(ig * 4 + r) * 33 + k] * mv;
        }
        __syncthreads();
#pragma unroll
        for (int r = 0; r < 4; r++) Xp[ib * 1056 + (ig * 4 + r) * 33 + lane] = -acc2[r];
        __syncthreads();
    }
    // epilogue: write bf16 hi/lo (only lower-triangular panels; upper stays 0)
    for (int ib = jb; ib < 16; ib++)
        for (int e = t; e < 1024; e += 256) {
            int r = e / 32, cc = e % 32;
            float val = Xp[ib * 1056 + r * 33 + cc];
            __nv_bfloat16 h = __float2bfloat16(val);
            float lo = val - __bfloat162float(h);
            size_t gi = (size_t)c * D * D + (size_t)(ib * 32 + r) * D + jb * 32 + cc;
            g_Th[gi] = h;
            g_Tl[gi] = __float2bfloat16(lo);
        }
}

// ---------------- 9a. split Xq into bf16 hi/lo ------------------------------
__global__ void k_xsplit(const float* __restrict__ Xq) {
    int i = blockIdx.x * blockDim.x + threadIdx.x;
    float v = Xq[i];
    __nv_bfloat16 h = __float2bfloat16(v);
    g_Xh[i] = h;
    g_Xl[i] = __float2bfloat16(v - __bfloat162float(h));
}

// ---------------- 9b. v = T mu  and  |mu|^2 ---------------------------------
__global__ void k_v() {
    int c = blockIdx.x, i = threadIdx.x;
    const __nv_bfloat16* Th = &g_Th[(size_t)c * D * D + (size_t)i * D];
    const __nv_bfloat16* Tl = &g_Tl[(size_t)c * D * D + (size_t)i * D];
    const float* mu = &g_mu[c * D];
    float acc = 0.f;
    for (int j = 0; j <= i; j++)
        acc += (__bfloat162float(Th[j]) + __bfloat162float(Tl[j])) * mu[j];
    g_v[c * D + i] = acc;
    __shared__ float red[512];
    float mi = mu[i];
    red[i] = mi * mi;
    __syncthreads();
    for (int o = 256; o > 0; o >>= 1) {
        if (i < o) red[i] += red[i + o];
        __syncthreads();
    }
    if (i == 0) g_munorm[c] = red[0];
}

// ---------------- 9c. |x_q|^2 -----------------------------------------------
__global__ void k_xnorm(const float* __restrict__ Xq) {
    int w = threadIdx.x / 32, lane = threadIdx.x % 32;
    int q = blockIdx.x * 8 + w;
    const float4* row = (const float4*)&Xq[(size_t)q * D];
    float s = 0.f;
#pragma unroll
    for (int j = 0; j < 4; j++) {
        float4 v = row[lane + 32 * j];
        s += v.x * v.x + v.y * v.y + v.z * v.z + v.w * v.w;
    }
#pragma unroll
    for (int o = 16; o > 0; o >>= 1) s += __shfl_down_sync(0xffffffffu, s, o);
    if (lane == 0) g_xnorm[q] = s;
}

// ---------------- 9d. dot[q][c] = x_q . mu_c --------------------------------
__global__ void k_dot(const float* __restrict__ Xq) {
    int qt = blockIdx.x;  // 32 tiles of 64 queries
    __shared__ float Xs_[16][68], Ms[16][68];
    int t = threadIdx.x;
    int tq = t % 16, ti = t / 16;
    int lrow = t / 4, jg = t % 4;
    float acc[4][4] = {};
    for (int k0 = 0; k0 < D; k0 += 16) {
        float4 a = *(const float4*)&Xq[(size_t)(qt * 64 + lrow) * D + k0 + jg * 4];
        float4 b = *(const float4*)&g_mu[lrow * D + k0 + jg * 4];
        __syncthreads();
        Xs_[jg * 4 + 0][lrow] = a.x; Xs_[jg * 4 + 1][lrow] = a.y;
        Xs_[jg * 4 + 2][lrow] = a.z; Xs_[jg * 4 + 3][lrow] = a.w;
        Ms[jg * 4 + 0][lrow] = b.x; Ms[jg * 4 + 1][lrow] = b.y;
        Ms[jg * 4 + 2][lrow] = b.z; Ms[jg * 4 + 3][lrow] = b.w;
        __syncthreads();
#pragma unroll
        for (int k = 0; k < 16; k++) {
            float4 av = *(const float4*)&Xs_[k][tq * 4];
            float4 bv = *(const float4*)&Ms[k][ti * 4];
            float a4[4] = {av.x, av.y, av.z, av.w};
            float b4[4] = {bv.x, bv.y, bv.z, bv.w};
#pragma unroll
            for (int r = 0; r < 4; r++)
#pragma unroll
                for (int s2 = 0; s2 < 4; s2++) acc[r][s2] += a4[r] * b4[s2];
        }
    }
#pragma unroll
    for (int r = 0; r < 4; r++)
#pragma unroll
        for (int s2 = 0; s2 < 4; s2++)
            g_dot[(size_t)(qt * 64 + tq * 4 + r) * C + ti * 4 + s2] = acc[r][s2];
}

// ---------------- 10. tensor-core Mahalanobis + logits ----------------------
// CTA: 128 queries x TWO classes (A tiles shared). 64-wide k-chunks.
// Warps 4x2 over 128x128 output; per-thread epilogue (one thread = one (q,c)).
__global__ void __launch_bounds__(256) k_logits_mma(const float* __restrict__ nu,
                                                    float* __restrict__ out) {
    int qt = blockIdx.x;          // 16 tiles of 128 queries
    int c0 = blockIdx.y * 2;      // class pair
    int q0 = qt * 128;
    int t = threadIdx.x, wid = t / 32;
    int warp_m = wid % 4, warp_n = wid / 4;    // 32-row x 64-col warp tile

    extern __shared__ __align__(16) unsigned char dynbuf[];
    __nv_bfloat16* As_h = (__nv_bfloat16*)dynbuf;           // 128 x PADK
    __nv_bfloat16* As_l = As_h + 128 * PADK;
    __nv_bfloat16* Bs_h = As_l + 128 * PADK;                // 128 x PADK (2 classes)
    __nv_bfloat16* Bs_l = Bs_h + 128 * PADK;
    float* Ys = (float*)dynbuf;                             // 128 x YSTR (overlay)
    __shared__ float sv[2][512];

    // preload v for both classes
    for (int l = t; l < 1024; l += 256)
        sv[l >> 9][l & 511] = g_v[(size_t)(c0 + (l >> 9)) * D + (l & 511)];

    int qe = t >> 1, half = t & 1;
    float distp = 0.f;

    for (int it = 0; it < 8; it++) {
        wmma::fragment<wmma::accumulator, 16, 16, 16, float> acc[2][4];
#pragma unroll
        for (int r = 0; r < 2; r++)
#pragma unroll
            for (int s2 = 0; s2 < 4; s2++) wmma::fill_fragment(acc[r][s2], 0.f);

        int Klim = (it + 1) * 64;
        for (int k0 = 0; k0 < Klim; k0 += 64) {
            __syncthreads();
            // A tiles: 128 x 64 hi & lo
#pragma unroll
            for (int l = t; l < 1024; l += 256) {
                int row = l >> 3, ch = l & 7;
                size_t g = (size_t)(q0 + row) * D + k0 + ch * 8;
                *(uint4*)&As_h[row * PADK + ch * 8] = *(const uint4*)&g_Xh[g];
                *(uint4*)&As_l[row * PADK + ch * 8] = *(const uint4*)&g_Xl[g];
            }
            // B tiles: rows 0-63 class c0, rows 64-127 class c0+1
#pragma unroll
            for (int l = t; l < 1024; l += 256) {
                int row = l >> 3, ch = l & 7;
                int cls = row >> 6;
                size_t g = (size_t)(c0 + cls) * D * D
                         + (size_t)(it * 64 + (row & 63)) * D + k0 + ch * 8;
                *(uint4*)&Bs_h[row * PADK + ch * 8] = *(const uint4*)&g_Th[g];
                *(uint4*)&Bs_l[row * PADK + ch * 8] = *(const uint4*)&g_Tl[g];
            }
            __syncthreads();
#pragma unroll
            for (int kk = 0; kk < 64; kk += 16) {
                wmma::fragment<wmma::matrix_a, 16, 16, 16, __nv_bfloat16, wmma::row_major> ah[2], al[2];
                wmma::fragment<wmma::matrix_b, 16, 16, 16, __nv_bfloat16, wmma::col_major> bh[4], bl[4];
#pragma unroll
                for (int r = 0; r < 2; r++) {
                    wmma::load_matrix_sync(ah[r], &As_h[(warp_m * 32 + r * 16) * PADK + kk], PADK);
                    wmma::load_matrix_sync(al[r], &As_l[(warp_m * 32 + r * 16) * PADK + kk], PADK);
                }
#pragma unroll
                for (int s2 = 0; s2 < 4; s2++) {
                    wmma::load_matrix_sync(bh[s2], &Bs_h[(warp_n * 64 + s2 * 16) * PADK + kk], PADK);
                    wmma::load_matrix_sync(bl[s2], &Bs_l[(warp_n * 64 + s2 * 16) * PADK + kk], PADK);
                }
#pragma unroll
                for (int r = 0; r < 2; r++)
#pragma unroll
                    for (int s2 = 0; s2 < 4; s2++) {
                        wmma::mma_sync(acc[r][s2], ah[r], bh[s2], acc[r][s2]);
                        wmma::mma_sync(acc[r][s2], ah[r], bl[s2], acc[r][s2]);
                        wmma::mma_sync(acc[r][s2], al[r], bh[s2], acc[r][s2]);
                    }
            }
        }
        __syncthreads();   // all warps done with A/B smem; overlay Y
#pragma unroll
        for (int r = 0; r < 2; r++)
#pragma unroll
            for (int s2 = 0; s2 < 4; s2++)
                wmma::store_matrix_sync(&Ys[(warp_m * 32 + r * 16) * YSTR + warp_n * 64 + s2 * 16],
                                        acc[r][s2], YSTR, wmma::mem_row_major);
        __syncthreads();
        {   // (u - v)^2 for this i-tile; thread -> (query qe, class half)
            const float* yrow = &Ys[qe * YSTR + half * 64];
            const float* vv = &sv[half][it * 64];
#pragma unroll
            for (int i = 0; i < 64; i++) {
                float dv = yrow[i] - vv[i];
                distp += dv * dv;
            }
        }
        __syncthreads();   // before next i-tile overwrites the overlay
    }

    {   // per-thread logit
        int q = q0 + qe;
        int c = c0 + half;
        float l2 = g_xnorm[q] - 2.f * g_dot[(size_t)q * C + c] + g_munorm[c];
        float dist = (1.f - REGP) * distp + REGP * l2;
        float nuv = dev_nu(nu);
        float common = nuv + (float)S + 1.f - (float)D;
        float bias = lgammaf(0.5f * (common + (float)D)) - lgammaf(0.5f * common)
                   - 0.5f * (float)D * logf(common) - 0.5f * g_logdet[c];
        out[(size_t)q * C + c] = bias - 0.5f * (common + (float)D) * log1pf(dist / common);
    }
}

// ---------------- launch -----------------------------------------------------
extern "C" void kernel_launch(void* const* d_in, const int* in_sizes, int n_in,
                              void* d_out, int out_size) {
    const float* Xs    = (const float*)d_in[0];
    const int*   labels= (const int*)d_in[1];
    const float* Xq    = (const float*)d_in[2];
    const float* m     = (const float*)d_in[3];
    const float* kappa = (const float*)d_in[4];
    const float* nu    = (const float*)d_in[5];
    const float* tdiag = (const float*)d_in[6];
    const float* tlow  = (const float*)d_in[7];
    float* out = (float*)d_out;

    cudaFuncSetAttribute(k_logits_mma, cudaFuncAttributeMaxDynamicSharedMemorySize, 73728);
    void* dummy_ptr = nullptr;
    cudaGetSymbolAddress(&dummy_ptr, g_dummy);

    k_bucket<<<4, 256>>>(labels);
    k_build_L<<<D, D>>>(tdiag, tlow);
    k_base<<<dim3(8, 8), 256>>>(m, kappa);

    // ---- PROBE: duplicate of the dominant GEMM kernel placed as the 4th
    // user launch so the fixed `-s 5 -c 1` ncu capture lands on it. Reads
    // stale-but-deterministic scratch state; writes only g_dummy (never
    // validated). Cost of this launch == true cost of the real k_logits_mma,
    // so dur_us - 2058 directly measures it as well.
    k_logits_mma<<<dim3(Q / 128, C / 2), 256, 73728>>>(nu, (float*)dummy_ptr);

    k_mu<<<C, D>>>(Xs, m, kappa);
    k_sigma<<<dim3(8, 8, C), 256>>>(Xs, kappa, nu);

    // stepped Cholesky: full-chip trailing updates
    for (int kb = 0; kb < 16; kb++) {
        k_chol_panel<<<C, 256>>>(kb);
        int nb = 15 - kb;
        if (nb > 0)
            k_chol_trail<<<dim3(nb * (nb + 1) / 2, C), 64>>>(kb);
    }

    k_dinv<<<C, 512>>>();
    cudaFuncSetAttribute(k_tinv, cudaFuncAttributeMaxDynamicSharedMemorySize, 76032);
    k_tinv<<<dim3(16, C), 256, 76032>>>();
    k_xsplit<<<(Q * D) / 256, 256>>>(Xq);
    k_v<<<C, 512>>>();
    k_xnorm<<<Q / 8, 256>>>(Xq);
    k_dot<<<Q / 64, 256>>>(Xq);
    k_logits_mma<<<dim3(Q / 128, C / 2), 256, 73728>>>(nu, out);
}

// round 15
// speedup vs baseline: 1.3082x; 1.3082x over previous
#include <cuda_runtime.h>
#include <cuda_bf16.h>
#include <mma.h>
#include <math.h>

using namespace nvcuda;

#define D 512
#define C 64
#define S 16
#define NS 1024
#define Q 2048
#define REGP 0.1f
#define PADK 72    // bf16 smem row stride for 64-wide k-chunks (mult of 8)
#define YSTR 136   // fp32 Y smem row stride (MUST be mult of 4 for wmma store)

// ---------------- scratch (device globals: zero-initialized at load) --------
__device__ float g_L[D * D];
__device__ float g_base[D * D];
__device__ float g_mu[C * D];
__device__ float g_logdet[C];
__device__ int   g_idx[NS];
__device__ float g_sigma[(size_t)C * D * D];      // sigma -> cholesky L (lower)
__device__ float g_dinv[C * 16 * 32 * 32];        // inverses of 32x32 diag blocks
__device__ __nv_bfloat16 g_Th[(size_t)C * D * D]; // T = inv(L), bf16 hi (upper stays 0)
__device__ __nv_bfloat16 g_Tl[(size_t)C * D * D]; // T bf16 lo
__device__ __nv_bfloat16 g_Xh[(size_t)Q * D];     // Xq bf16 hi
__device__ __nv_bfloat16 g_Xl[(size_t)Q * D];     // Xq bf16 lo
__device__ float g_v[C * D];                      // v_c = T_c mu_c
__device__ float g_munorm[C];
__device__ float g_xnorm[Q];
__device__ float g_dot[(size_t)Q * C];            // Xq . mu_c

__device__ __forceinline__ float dev_kap(const float* kappa) {
    return fabsf(*kappa) + 1e-6f;
}
__device__ __forceinline__ float dev_nu(const float* nu) {
    float v = *nu;
    float lo = (float)(D - 1) + 1e-6f;
    return v < lo ? lo : v;
}

// ---------------- 1. deterministic stable bucketing ------------------------
__global__ void k_bucket(const int* __restrict__ labels) {
    int i = blockIdx.x * blockDim.x + threadIdx.x;
    if (i >= NS) return;
    int lab = labels[i];
    int pos = 0;
    for (int p = 0; p < i; p++) pos += (labels[p] == lab) ? 1 : 0;
    g_idx[lab * S + pos] = i;
}

// ---------------- 2. materialize L ------------------------------------------
__global__ void k_build_L(const float* __restrict__ tdiag, const float* __restrict__ tlow) {
    int i = blockIdx.x, j = threadIdx.x;
    float v;
    if (j == i)      v = fabsf(tdiag[i]);
    else if (j < i)  v = tlow[i * D + j];
    else             v = 0.f;
    g_L[i * D + j] = v;
}

// ---------------- 3. base = L L^T + kap m m^T (lower 64x64 tiles) -----------
__global__ void k_base(const float* __restrict__ m, const float* __restrict__ kappa) {
    int bi = blockIdx.x, bj = blockIdx.y;
    if (bi < bj) return;
    __shared__ float As[16][68], Bsm[16][68];
    int t = threadIdx.x;
    int tq = t % 16, ti = t / 16;
    int lrow = t / 4, jg = t % 4;
    float acc[4][4] = {};
    for (int k0 = 0; k0 < D; k0 += 16) {
        float4 a = *(const float4*)&g_L[(bi * 64 + lrow) * D + k0 + jg * 4];
        float4 b = *(const float4*)&g_L[(bj * 64 + lrow) * D + k0 + jg * 4];
        __syncthreads();
        As[jg * 4 + 0][lrow] = a.x; As[jg * 4 + 1][lrow] = a.y;
        As[jg * 4 + 2][lrow] = a.z; As[jg * 4 + 3][lrow] = a.w;
        Bsm[jg * 4 + 0][lrow] = b.x; Bsm[jg * 4 + 1][lrow] = b.y;
        Bsm[jg * 4 + 2][lrow] = b.z; Bsm[jg * 4 + 3][lrow] = b.w;
        __syncthreads();
#pragma unroll
        for (int k = 0; k < 16; k++) {
            float4 av = *(const float4*)&As[k][tq * 4];
            float4 bv = *(const float4*)&Bsm[k][ti * 4];
            float a4[4] = {av.x, av.y, av.z, av.w};
            float b4[4] = {bv.x, bv.y, bv.z, bv.w};
#pragma unroll
            for (int r = 0; r < 4; r++)
#pragma unroll
                for (int s2 = 0; s2 < 4; s2++) acc[r][s2] += a4[r] * b4[s2];
        }
    }
    float kap = dev_kap(kappa);
#pragma unroll
    for (int r = 0; r < 4; r++) {
        int di = bi * 64 + tq * 4 + r;
#pragma unroll
        for (int s2 = 0; s2 < 4; s2++) {
            int ej = bj * 64 + ti * 4 + s2;
            g_base[di * D + ej] = acc[r][s2] + kap * m[di] * m[ej];
        }
    }
}

// ---------------- 4. class means -> mu --------------------------------------
__global__ void k_mu(const float* __restrict__ Xs, const float* __restrict__ m,
                     const float* __restrict__ kappa) {
    int c = blockIdx.x, d = threadIdx.x;
    float s = 0.f;
#pragma unroll
    for (int ss = 0; ss < S; ss++) s += Xs[(size_t)g_idx[c * S + ss] * D + d];
    float mean = s / (float)S;
    float kap = dev_kap(kappa);
    g_mu[c * D + d] = (kap / (kap + (float)S)) * m[d] + ((float)S / (kap + (float)S)) * mean;
}

// ---------------- 5. sigma[c] (lower 64x64 tiles) ---------------------------
__global__ void k_sigma(const float* __restrict__ Xs, const float* __restrict__ kappa,
                        const float* __restrict__ nu) {
    int bi = blockIdx.x, bj = blockIdx.y, c = blockIdx.z;
    if (bi < bj) return;
    __shared__ float Xi[16][68], Xj[16][68];
    int t = threadIdx.x;
    int srow = t / 16, cg = t % 16;
    {
        int gi = g_idx[c * S + srow];
        float4 a = *(const float4*)&Xs[(size_t)gi * D + bi * 64 + cg * 4];
        float4 b = *(const float4*)&Xs[(size_t)gi * D + bj * 64 + cg * 4];
        Xi[srow][cg * 4 + 0] = a.x; Xi[srow][cg * 4 + 1] = a.y;
        Xi[srow][cg * 4 + 2] = a.z; Xi[srow][cg * 4 + 3] = a.w;
        Xj[srow][cg * 4 + 0] = b.x; Xj[srow][cg * 4 + 1] = b.y;
        Xj[srow][cg * 4 + 2] = b.z; Xj[srow][cg * 4 + 3] = b.w;
    }
    __syncthreads();
    int tq = t % 16, ti = t / 16;
    float acc[4][4] = {};
#pragma unroll
    for (int s = 0; s < 16; s++) {
        float4 av = *(const float4*)&Xi[s][tq * 4];
        float4 bv = *(const float4*)&Xj[s][ti * 4];
        float a4[4] = {av.x, av.y, av.z, av.w};
        float b4[4] = {bv.x, bv.y, bv.z, bv.w};
#pragma unroll
        for (int r = 0; r < 4; r++)
#pragma unroll
            for (int s2 = 0; s2 < 4; s2++) acc[r][s2] += a4[r] * b4[s2];
    }
    float kap = dev_kap(kappa);
    float nuv = dev_nu(nu);
    float kS = kap + (float)S;
    float scale = (kS + 1.f) / ((nuv + (float)S - (float)D + 1.f) * kS);
    float* sig = &g_sigma[(size_t)c * D * D];
#pragma unroll
    for (int r = 0; r < 4; r++) {
        int di = bi * 64 + tq * 4 + r;
        float mud = g_mu[c * D + di];
#pragma unroll
        for (int s2 = 0; s2 < 4; s2++) {
            int ej = bj * 64 + ti * 4 + s2;
            float v = g_base[di * D + ej] + acc[r][s2] - kS * mud * g_mu[c * D + ej];
            sig[(size_t)di * D + ej] = v * scale;
        }
    }
}

// ---------------- 6a. Cholesky panel step (diag factor + column solve) ------
__global__ void k_chol_panel(int kb) {
    int c = blockIdx.x;
    float* A = &g_sigma[(size_t)c * D * D];
    __shared__ float Ds[32][33];
    __shared__ float s_ld;
    int t = threadIdx.x;  // 256

    for (int e = t; e < 1024; e += 256) {
        int r = e / 32, cc = e % 32;
        Ds[r][cc] = A[(size_t)(kb * 32 + r) * D + kb * 32 + cc];
    }
    __syncthreads();
    if (t < 32) {
        int lane = t;
        for (int k = 0; k < 32; k++) {
            if (lane == k) Ds[k][k] = sqrtf(Ds[k][k]);
            __syncwarp();
            if (lane > k) Ds[lane][k] /= Ds[k][k];
            __syncwarp();
            for (int j = k + 1; j <= lane; j++)
                Ds[lane][j] -= Ds[lane][k] * Ds[j][k];
            __syncwarp();
        }
        float lv = logf(Ds[lane][lane]);
#pragma unroll
        for (int o = 16; o > 0; o >>= 1) lv += __shfl_down_sync(0xffffffffu, lv, o);
        if (lane == 0) s_ld = lv;
    }
    __syncthreads();
    for (int e = t; e < 1024; e += 256) {
        int r = e / 32, cc = e % 32;
        A[(size_t)(kb * 32 + r) * D + kb * 32 + cc] = (cc <= r) ? Ds[r][cc] : 0.f;
    }
    // panel rows below: solve x * Ds^T = a
    for (int r = (kb + 1) * 32 + t; r < D; r += 256) {
        float a[32];
#pragma unroll
        for (int j = 0; j < 32; j++) a[j] = A[(size_t)r * D + kb * 32 + j];
#pragma unroll
        for (int j = 0; j < 32; j++) {
            float sacc = a[j];
#pragma unroll
            for (int k2 = 0; k2 < 32; k2++)
                if (k2 < j) sacc -= a[k2] * Ds[j][k2];
            a[j] = sacc / Ds[j][j];
        }
#pragma unroll
        for (int j = 0; j < 32; j++) A[(size_t)r * D + kb * 32 + j] = a[j];
    }
    if (t == 0) {
        if (kb == 0) g_logdet[c] = 2.f * s_ld;
        else         g_logdet[c] += 2.f * s_ld;
    }
}

// ---------------- 6b. Cholesky trailing step: A[ib,jb] -= Pi Pj^T -----------
__global__ void __launch_bounds__(64) k_chol_trail(int kb) {
    int c = blockIdx.y;
    int p = blockIdx.x;
    int ib = kb + 1, rem = p;
    while (rem >= ib - kb) { rem -= (ib - kb); ib++; }
    int jb = kb + 1 + rem;

    float* A = &g_sigma[(size_t)c * D * D];
    __shared__ float Pi[32][33], Pj[32][33];
    int t = threadIdx.x;
    for (int e = t; e < 1024; e += 64) {
        int r = e / 32, cc = e % 32;
        Pi[r][cc] = A[(size_t)(ib * 32 + r) * D + kb * 32 + cc];
        Pj[r][cc] = A[(size_t)(jb * 32 + r) * D + kb * 32 + cc];
    }
    __syncthreads();
    int r0 = (t / 8) * 4, c0 = (t % 8) * 4;
    float acc[4][4] = {};
#pragma unroll
    for (int k2 = 0; k2 < 32; k2++) {
        float pi0 = Pi[r0 + 0][k2], pi1 = Pi[r0 + 1][k2];
        float pi2 = Pi[r0 + 2][k2], pi3 = Pi[r0 + 3][k2];
        float pj0 = Pj[c0 + 0][k2], pj1 = Pj[c0 + 1][k2];
        float pj2 = Pj[c0 + 2][k2], pj3 = Pj[c0 + 3][k2];
        acc[0][0] += pi0 * pj0; acc[0][1] += pi0 * pj1; acc[0][2] += pi0 * pj2; acc[0][3] += pi0 * pj3;
        acc[1][0] += pi1 * pj0; acc[1][1] += pi1 * pj1; acc[1][2] += pi1 * pj2; acc[1][3] += pi1 * pj3;
        acc[2][0] += pi2 * pj0; acc[2][1] += pi2 * pj1; acc[2][2] += pi2 * pj2; acc[2][3] += pi2 * pj3;
        acc[3][0] += pi3 * pj0; acc[3][1] += pi3 * pj1; acc[3][2] += pi3 * pj2; acc[3][3] += pi3 * pj3;
    }
#pragma unroll
    for (int r = 0; r < 4; r++)
#pragma unroll
        for (int s2 = 0; s2 < 4; s2++)
            A[(size_t)(ib * 32 + r0 + r) * D + jb * 32 + c0 + s2] -= acc[r][s2];
}

// ---------------- 7. invert 32x32 diagonal blocks of L ----------------------
__global__ void k_dinv() {
    int c = blockIdx.x;
    int blk = threadIdx.x / 32, lane = threadIdx.x % 32;
    const float* Lb = &g_sigma[(size_t)c * D * D + (size_t)(blk * 32) * D + blk * 32];
    float x[32];
#pragma unroll
    for (int i = 0; i < 32; i++) x[i] = 0.f;
#pragma unroll
    for (int i = 0; i < 32; i++) {
        float sacc = (i == lane) ? 1.f : 0.f;
#pragma unroll
        for (int k = 0; k < 32; k++)
            if (k < i) sacc -= Lb[(size_t)i * D + k] * x[k];
        x[i] = (i < lane) ? 0.f : sacc / Lb[(size_t)i * D + i];
    }
    float* out = &g_dinv[((size_t)c * 16 + blk) * 1024];
#pragma unroll
    for (int i = 0; i < 32; i++) out[i * 32 + lane] = x[i];
}

// ---------------- 8. T = inv(L) -> bf16 hi/lo split -------------------------
__global__ void k_tinv() {
    int jb = blockIdx.x, c = blockIdx.y;
    extern __shared__ float sm[];
    float* Xp = sm;                 // [16][32][33]
    float* Ls = sm + 16 * 1056;     // [32][33]
    float* Msh = Ls + 1056;         // [32][33]
    int t = threadIdx.x;
    int lane = t % 32, ig = t / 32;
    const float* A = &g_sigma[(size_t)c * D * D];
    const float* Dv = &g_dinv[(size_t)c * 16 * 1024];

    for (int e = t; e < 1024; e += 256) {
        int r = e / 32, cc = e % 32;
        Xp[jb * 1056 + r * 33 + cc] = Dv[jb * 1024 + r * 32 + cc];
    }
    __syncthreads();

    for (int ib = jb + 1; ib < 16; ib++) {
        float acc[4] = {0.f, 0.f, 0.f, 0.f};
        for (int kb = jb; kb < ib; kb++) {
            __syncthreads();
            for (int e = t; e < 1024; e += 256) {
                int r = e / 32, cc = e % 32;
                Ls[r * 33 + cc] = A[(size_t)(ib * 32 + r) * D + kb * 32 + cc];
            }
            __syncthreads();
#pragma unroll
            for (int k = 0; k < 32; k++) {
                float xv = Xp[kb * 1056 + k * 33 + lane];
#pragma unroll
                for (int r = 0; r < 4; r++) acc[r] += Ls[(ig * 4 + r) * 33 + k] * xv;
            }
        }
        __syncthreads();
#pragma unroll
        for (int r = 0; r < 4; r++) Msh[(ig * 4 + r) * 33 + lane] = acc[r];
        for (int e = t; e < 1024; e += 256) {
            int r = e / 32, cc = e % 32;
            Ls[r * 33 + cc] = Dv[ib * 1024 + r * 32 + cc];
        }
        __syncthreads();
        float acc2[4] = {0.f, 0.f, 0.f, 0.f};
#pragma unroll
        for (int k = 0; k < 32; k++) {
            float mv = Msh[k * 33 + lane];
#pragma unroll
            for (int r = 0; r < 4; r++) acc2[r] += Ls[(ig * 4 + r) * 33 + k] * mv;
        }
        __syncthreads();
#pragma unroll
        for (int r = 0; r < 4; r++) Xp[ib * 1056 + (ig * 4 + r) * 33 + lane] = -acc2[r];
        __syncthreads();
    }
    // epilogue: write bf16 hi/lo (only lower-triangular panels; upper stays 0)
    for (int ib = jb; ib < 16; ib++)
        for (int e = t; e < 1024; e += 256) {
            int r = e / 32, cc = e % 32;
            float val = Xp[ib * 1056 + r * 33 + cc];
            __nv_bfloat16 h = __float2bfloat16(val);
            float lo = val - __bfloat162float(h);
            size_t gi = (size_t)c * D * D + (size_t)(ib * 32 + r) * D + jb * 32 + cc;
            g_Th[gi] = h;
            g_Tl[gi] = __float2bfloat16(lo);
        }
}

// ---------------- 9a. split Xq into bf16 hi/lo ------------------------------
__global__ void k_xsplit(const float* __restrict__ Xq) {
    int i = blockIdx.x * blockDim.x + threadIdx.x;
    float v = Xq[i];
    __nv_bfloat16 h = __float2bfloat16(v);
    g_Xh[i] = h;
    g_Xl[i] = __float2bfloat16(v - __bfloat162float(h));
}

// ---------------- 9b. v = T mu (warp-per-row, coalesced) and |mu|^2 ---------
__global__ void k_v() {
    int c = blockIdx.x, t = threadIdx.x;     // 512 threads = 16 warps
    int w = t / 32, lane = t % 32;
    __shared__ float smu[512];
    smu[t] = g_mu[c * D + t];
    __syncthreads();
    const __nv_bfloat16* Th = &g_Th[(size_t)c * D * D];
    const __nv_bfloat16* Tl = &g_Tl[(size_t)c * D * D];
    // warp w handles rows w, w+16, ... ; lanes stride columns (coalesced)
    for (int r = w; r < D; r += 16) {
        float acc = 0.f;
        for (int j = lane; j <= r; j += 32)
            acc += (__bfloat162float(Th[(size_t)r * D + j]) +
                    __bfloat162float(Tl[(size_t)r * D + j])) * smu[j];
#pragma unroll
        for (int o = 16; o > 0; o >>= 1) acc += __shfl_down_sync(0xffffffffu, acc, o);
        if (lane == 0) g_v[c * D + r] = acc;
    }
    // |mu|^2
    __shared__ float red[512];
    red[t] = smu[t] * smu[t];
    __syncthreads();
    for (int o = 256; o > 0; o >>= 1) {
        if (t < o) red[t] += red[t + o];
        __syncthreads();
    }
    if (t == 0) g_munorm[c] = red[0];
}

// ---------------- 9c. |x_q|^2 -----------------------------------------------
__global__ void k_xnorm(const float* __restrict__ Xq) {
    int w = threadIdx.x / 32, lane = threadIdx.x % 32;
    int q = blockIdx.x * 8 + w;
    const float4* row = (const float4*)&Xq[(size_t)q * D];
    float s = 0.f;
#pragma unroll
    for (int j = 0; j < 4; j++) {
        float4 v = row[lane + 32 * j];
        s += v.x * v.x + v.y * v.y + v.z * v.z + v.w * v.w;
    }
#pragma unroll
    for (int o = 16; o > 0; o >>= 1) s += __shfl_down_sync(0xffffffffu, s, o);
    if (lane == 0) g_xnorm[q] = s;
}

// ---------------- 9d. dot[q][c] = x_q . mu_c --------------------------------
__global__ void k_dot(const float* __restrict__ Xq) {
    int qt = blockIdx.x;  // 32 tiles of 64 queries
    __shared__ float Xs_[16][68], Ms[16][68];
    int t = threadIdx.x;
    int tq = t % 16, ti = t / 16;
    int lrow = t / 4, jg = t % 4;
    float acc[4][4] = {};
    for (int k0 = 0; k0 < D; k0 += 16) {
        float4 a = *(const float4*)&Xq[(size_t)(qt * 64 + lrow) * D + k0 + jg * 4];
        float4 b = *(const float4*)&g_mu[lrow * D + k0 + jg * 4];
        __syncthreads();
        Xs_[jg * 4 + 0][lrow] = a.x; Xs_[jg * 4 + 1][lrow] = a.y;
        Xs_[jg * 4 + 2][lrow] = a.z; Xs_[jg * 4 + 3][lrow] = a.w;
        Ms[jg * 4 + 0][lrow] = b.x; Ms[jg * 4 + 1][lrow] = b.y;
        Ms[jg * 4 + 2][lrow] = b.z; Ms[jg * 4 + 3][lrow] = b.w;
        __syncthreads();
#pragma unroll
        for (int k = 0; k < 16; k++) {
            float4 av = *(const float4*)&Xs_[k][tq * 4];
            float4 bv = *(const float4*)&Ms[k][ti * 4];
            float a4[4] = {av.x, av.y, av.z, av.w};
            float b4[4] = {bv.x, bv.y, bv.z, bv.w};
#pragma unroll
            for (int r = 0; r < 4; r++)
#pragma unroll
                for (int s2 = 0; s2 < 4; s2++) acc[r][s2] += a4[r] * b4[s2];
        }
    }
#pragma unroll
    for (int r = 0; r < 4; r++)
#pragma unroll
        for (int s2 = 0; s2 < 4; s2++)
            g_dot[(size_t)(qt * 64 + tq * 4 + r) * C + ti * 4 + s2] = acc[r][s2];
}

// ---------------- 10. tensor-core Mahalanobis + logits ----------------------
// CTA: 128 queries x TWO classes. 64-wide k-chunks. Warps 4x2 over 128x128.
// Register diet: B fragments loaded one column-pair at a time; capped at
// 2 CTAs/SM via __launch_bounds__ so 16 warps/SM hide wmma latency.
__global__ void __launch_bounds__(256, 2) k_logits_mma(const float* __restrict__ nu,
                                                       float* __restrict__ out) {
    int qt = blockIdx.x;          // 16 tiles of 128 queries
    int c0 = blockIdx.y * 2;      // class pair
    int q0 = qt * 128;
    int t = threadIdx.x, wid = t / 32;
    int warp_m = wid % 4, warp_n = wid / 4;    // 32-row x 64-col warp tile

    extern __shared__ __align__(16) unsigned char dynbuf[];
    __nv_bfloat16* As_h = (__nv_bfloat16*)dynbuf;           // 128 x PADK
    __nv_bfloat16* As_l = As_h + 128 * PADK;
    __nv_bfloat16* Bs_h = As_l + 128 * PADK;                // 128 x PADK (2 classes)
    __nv_bfloat16* Bs_l = Bs_h + 128 * PADK;
    float* Ys = (float*)dynbuf;                             // 128 x YSTR (overlay)
    __shared__ float sv[2][512];

    // preload v for both classes
    for (int l = t; l < 1024; l += 256)
        sv[l >> 9][l & 511] = g_v[(size_t)(c0 + (l >> 9)) * D + (l & 511)];

    int qe = t >> 1, half = t & 1;
    float distp = 0.f;

    for (int it = 0; it < 8; it++) {
        wmma::fragment<wmma::accumulator, 16, 16, 16, float> acc[2][4];
#pragma unroll
        for (int r = 0; r < 2; r++)
#pragma unroll
            for (int s2 = 0; s2 < 4; s2++) wmma::fill_fragment(acc[r][s2], 0.f);

        int Klim = (it + 1) * 64;
        for (int k0 = 0; k0 < Klim; k0 += 64) {
            __syncthreads();
            // A tiles: 128 x 64 hi & lo
#pragma unroll
            for (int l = t; l < 1024; l += 256) {
                int row = l >> 3, ch = l & 7;
                size_t g = (size_t)(q0 + row) * D + k0 + ch * 8;
                *(uint4*)&As_h[row * PADK + ch * 8] = *(const uint4*)&g_Xh[g];
                *(uint4*)&As_l[row * PADK + ch * 8] = *(const uint4*)&g_Xl[g];
            }
            // B tiles: rows 0-63 class c0, rows 64-127 class c0+1
#pragma unroll
            for (int l = t; l < 1024; l += 256) {
                int row = l >> 3, ch = l & 7;
                int cls = row >> 6;
                size_t g = (size_t)(c0 + cls) * D * D
                         + (size_t)(it * 64 + (row & 63)) * D + k0 + ch * 8;
                *(uint4*)&Bs_h[row * PADK + ch * 8] = *(const uint4*)&g_Th[g];
                *(uint4*)&Bs_l[row * PADK + ch * 8] = *(const uint4*)&g_Tl[g];
            }
            __syncthreads();
#pragma unroll
            for (int kk = 0; kk < 64; kk += 16) {
                wmma::fragment<wmma::matrix_a, 16, 16, 16, __nv_bfloat16, wmma::row_major> ah[2], al[2];
#pragma unroll
                for (int r = 0; r < 2; r++) {
                    wmma::load_matrix_sync(ah[r], &As_h[(warp_m * 32 + r * 16) * PADK + kk], PADK);
                    wmma::load_matrix_sync(al[r], &As_l[(warp_m * 32 + r * 16) * PADK + kk], PADK);
                }
#pragma unroll
                for (int s2 = 0; s2 < 4; s2++) {
                    wmma::fragment<wmma::matrix_b, 16, 16, 16, __nv_bfloat16, wmma::col_major> bh, bl;
                    wmma::load_matrix_sync(bh, &Bs_h[(warp_n * 64 + s2 * 16) * PADK + kk], PADK);
                    wmma::load_matrix_sync(bl, &Bs_l[(warp_n * 64 + s2 * 16) * PADK + kk], PADK);
#pragma unroll
                    for (int r = 0; r < 2; r++) {
                        wmma::mma_sync(acc[r][s2], ah[r], bh, acc[r][s2]);
                        wmma::mma_sync(acc[r][s2], ah[r], bl, acc[r][s2]);
                        wmma::mma_sync(acc[r][s2], al[r], bh, acc[r][s2]);
                    }
                }
            }
        }
        __syncthreads();   // all warps done with A/B smem; overlay Y
#pragma unroll
        for (int r = 0; r < 2; r++)
#pragma unroll
            for (int s2 = 0; s2 < 4; s2++)
                wmma::store_matrix_sync(&Ys[(warp_m * 32 + r * 16) * YSTR + warp_n * 64 + s2 * 16],
                                        acc[r][s2], YSTR, wmma::mem_row_major);
        __syncthreads();
        {   // (u - v)^2 for this i-tile; thread -> (query qe, class half)
            const float* yrow = &Ys[qe * YSTR + half * 64];
            const float* vv = &sv[half][it * 64];
#pragma unroll
            for (int i = 0; i < 64; i++) {
                float dv = yrow[i] - vv[i];
                distp += dv * dv;
            }
        }
        __syncthreads();   // before next i-tile overwrites the overlay
    }

    {   // per-thread logit
        int q = q0 + qe;
        int c = c0 + half;
        float l2 = g_xnorm[q] - 2.f * g_dot[(size_t)q * C + c] + g_munorm[c];
        float dist = (1.f - REGP) * distp + REGP * l2;
        float nuv = dev_nu(nu);
        float common = nuv + (float)S + 1.f - (float)D;
        float bias = lgammaf(0.5f * (common + (float)D)) - lgammaf(0.5f * common)
                   - 0.5f * (float)D * logf(common) - 0.5f * g_logdet[c];
        out[(size_t)q * C + c] = bias - 0.5f * (common + (float)D) * log1pf(dist / common);
    }
}

// ---------------- launch -----------------------------------------------------
extern "C" void kernel_launch(void* const* d_in, const int* in_sizes, int n_in,
                              void* d_out, int out_size) {
    const float* Xs    = (const float*)d_in[0];
    const int*   labels= (const int*)d_in[1];
    const float* Xq    = (const float*)d_in[2];
    const float* m     = (const float*)d_in[3];
    const float* kappa = (const float*)d_in[4];
    const float* nu    = (const float*)d_in[5];
    const float* tdiag = (const float*)d_in[6];
    const float* tlow  = (const float*)d_in[7];
    float* out = (float*)d_out;

    k_bucket<<<4, 256>>>(labels);
    k_build_L<<<D, D>>>(tdiag, tlow);
    k_base<<<dim3(8, 8), 256>>>(m, kappa);
    k_mu<<<C, D>>>(Xs, m, kappa);
    k_sigma<<<dim3(8, 8, C), 256>>>(Xs, kappa, nu);

    // stepped Cholesky: full-chip trailing updates
    for (int kb = 0; kb < 16; kb++) {
        k_chol_panel<<<C, 256>>>(kb);
        int nb = 15 - kb;
        if (nb > 0)
            k_chol_trail<<<dim3(nb * (nb + 1) / 2, C), 64>>>(kb);
    }

    k_dinv<<<C, 512>>>();
    cudaFuncSetAttribute(k_tinv, cudaFuncAttributeMaxDynamicSharedMemorySize, 76032);
    k_tinv<<<dim3(16, C), 256, 76032>>>();
    k_xsplit<<<(Q * D) / 256, 256>>>(Xq);
    k_v<<<C, 512>>>();
    k_xnorm<<<Q / 8, 256>>>(Xq);
    k_dot<<<Q / 64, 256>>>(Xq);
    cudaFuncSetAttribute(k_logits_mma, cudaFuncAttributeMaxDynamicSharedMemorySize, 73728);
    k_logits_mma<<<dim3(Q / 128, C / 2), 256, 73728>>>(nu, out);
}